// round 6
// baseline (speedup 1.0000x reference)
#include <cuda_runtime.h>
#include <cuda_fp16.h>
#include <math.h>
#include <stdint.h>

#define BB 4
#define NN 4096
#define DD 64
#define SHIFT 64.0f
#define L2E 1.4426950408889634f
#define TWO_L2E (2.0f * L2E)
#define NGL2E (-40000.0f * L2E)       /* -(1/sigma^2)*log2(e) */
#define STH 0.00226f                  /* dist^2 beyond which exp underflows */

#define ROWS 128
#define T_TILES 32
#define THREADS 512

/* ---- ce smem layout (bytes) ---- */
#define OFF_A    0                    /* 16384 */
#define OFF_B    16384                /* 2 x 16384 */
#define OFF_KV   49152                /* 2 x 512 */
#define OFF_RED  50176                /* 128 floats */
#define OFF_WSUM 50688                /* 16 floats */
#define SMEM_CE  50752

/* ---- pd smem layout (bytes) ---- */
#define PD_PX 0
#define PD_PY 16384
#define PD_PZ 32768
#define PD_RZ 49152                   /* 7*128 floats */
#define PD_RT (49152 + 3584)
#define SMEM_PD (49152 + 7168)

/* ---- device scratch ---- */
__device__ __align__(16) unsigned char g_f1h[BB * NN * 128];
__device__ __align__(16) unsigned char g_f2h[BB * NN * 128];
__device__ float g_kvt[BB * NN];      /* -L2E*n2, tile-blocked */
__device__ float g_rowk[BB * NN];     /* L2E*(SHIFT - n1) */
__device__ float g_n1[BB * NN];
__device__ float g_n2[BB * NN];
__device__ float g_pdz[BB * NN];
__device__ float g_pdt[BB * NN];
__device__ float g_cep[BB * 32];
__device__ float g_regp[64];

typedef unsigned long long ull;

/* ------------------------------- asm helpers ----------------------------- */
__device__ __forceinline__ uint32_t smem_u32(const void* p) {
    uint32_t a;
    asm("{ .reg .u64 t; cvta.to.shared.u64 t, %1; cvt.u32.u64 %0, t; }" : "=r"(a) : "l"(p));
    return a;
}
__device__ __forceinline__ float ex2_(float x) {
    float r;
    asm("ex2.approx.ftz.f32 %0, %1;" : "=f"(r) : "f"(x));
    return r;
}
__device__ __forceinline__ ull pk2(float a, float b) {
    ull r;
    asm("mov.b64 %0, {%1, %2};" : "=l"(r) : "f"(a), "f"(b));
    return r;
}
__device__ __forceinline__ float2 upk2(ull v) {
    float x, y;
    asm("mov.b64 {%0, %1}, %2;" : "=f"(x), "=f"(y) : "l"(v));
    return make_float2(x, y);
}
__device__ __forceinline__ ull add2_(ull a, ull b) {
    ull r;
    asm("add.rn.f32x2 %0, %1, %2;" : "=l"(r) : "l"(a), "l"(b));
    return r;
}
__device__ __forceinline__ ull mul2_(ull a, ull b) {
    ull r;
    asm("mul.rn.f32x2 %0, %1, %2;" : "=l"(r) : "l"(a), "l"(b));
    return r;
}
__device__ __forceinline__ ull fma2_(ull a, ull b, ull c) {
    ull r;
    asm("fma.rn.f32x2 %0, %1, %2, %3;" : "=l"(r) : "l"(a), "l"(b), "l"(c));
    return r;
}
#define CPA16(dst, src) \
    asm volatile("cp.async.cg.shared.global [%0], [%1], 16;" :: "r"(dst), "l"(src))
#define CPA_COMMIT() asm volatile("cp.async.commit_group;" ::: "memory")
#define CPA_WAIT0()  asm volatile("cp.async.wait_group 0;" ::: "memory")

#define LDSM4(r, addr) \
    asm volatile("ldmatrix.sync.aligned.m8n8.x4.shared.b16 {%0,%1,%2,%3}, [%4];" \
        : "=r"((r)[0]), "=r"((r)[1]), "=r"((r)[2]), "=r"((r)[3]) : "r"(addr))

#define MMA16816(c, a, b0_, b1_) \
    asm volatile("mma.sync.aligned.m16n8k16.row.col.f32.f16.f16.f32 " \
        "{%0,%1,%2,%3},{%4,%5,%6,%7},{%8,%9},{%0,%1,%2,%3};" \
        : "+f"((c)[0]), "+f"((c)[1]), "+f"((c)[2]), "+f"((c)[3]) \
        : "r"((a)[0]), "r"((a)[1]), "r"((a)[2]), "r"((a)[3]), "r"(b0_), "r"(b1_))

/* ------------------------------- prep kernel ----------------------------- */
__device__ __forceinline__ uint4 cvt8h(const float* f) {
    uint32_t h[4];
#pragma unroll
    for (int i = 0; i < 4; i++) {
        __half2 hh = __floats2half2_rn(f[2 * i], f[2 * i + 1]);
        h[i] = *reinterpret_cast<uint32_t*>(&hh);
    }
    return make_uint4(h[0], h[1], h[2], h[3]);
}

__global__ void __launch_bounds__(256)
prep_kernel(const float* __restrict__ f1, const float* __restrict__ f2)
{
    __shared__ float wsum[8];
    const int tid = threadIdx.x;
    const int row = blockIdx.x * 256 + tid;        /* 0 .. B*NN-1 */
    const int b = row >> 12, n = row & (NN - 1);
    const int t = n >> 7, rin = n & 127;
    const size_t tb = ((size_t)(b * T_TILES + t)) * 16384 + (size_t)rin * 128;
    const int sw = rin & 7;

    float f[DD];
    float n1 = 0.f, n2 = 0.f;
    {
        const float4* v = (const float4*)(f1 + (size_t)row * DD);
#pragma unroll
        for (int j = 0; j < DD / 4; j++) {
            float4 x = v[j];
            f[4 * j] = x.x; f[4 * j + 1] = x.y; f[4 * j + 2] = x.z; f[4 * j + 3] = x.w;
            n1 = fmaf(x.x, x.x, n1); n1 = fmaf(x.y, x.y, n1);
            n1 = fmaf(x.z, x.z, n1); n1 = fmaf(x.w, x.w, n1);
        }
#pragma unroll
        for (int c = 0; c < 8; c++)
            *reinterpret_cast<uint4*>(g_f1h + tb + (size_t)(((c ^ sw) << 4))) = cvt8h(f + 8 * c);
    }
    {
        const float4* v = (const float4*)(f2 + (size_t)row * DD);
#pragma unroll
        for (int j = 0; j < DD / 4; j++) {
            float4 x = v[j];
            f[4 * j] = x.x; f[4 * j + 1] = x.y; f[4 * j + 2] = x.z; f[4 * j + 3] = x.w;
            n2 = fmaf(x.x, x.x, n2); n2 = fmaf(x.y, x.y, n2);
            n2 = fmaf(x.z, x.z, n2); n2 = fmaf(x.w, x.w, n2);
        }
#pragma unroll
        for (int c = 0; c < 8; c++)
            *reinterpret_cast<uint4*>(g_f2h + tb + (size_t)(((c ^ sw) << 4))) = cvt8h(f + 8 * c);
    }
    g_rowk[row] = L2E * (SHIFT - n1);
    g_n1[row] = n1;
    g_n2[row] = n2;
    g_kvt[(b * T_TILES + t) * 128 + rin] = -L2E * n2;

    /* reg loss partial (per block, no atomics) */
    float s = n1 + n2;
#pragma unroll
    for (int o = 16; o > 0; o >>= 1) s += __shfl_down_sync(0xffffffffu, s, o);
    if ((tid & 31) == 0) wsum[tid >> 5] = s;
    __syncthreads();
    if (tid < 8) {
        float v = wsum[tid];
        v += __shfl_down_sync(0xffu, v, 4);
        v += __shfl_down_sync(0xffu, v, 2);
        v += __shfl_down_sync(0xffu, v, 1);
        if (tid == 0) g_regp[blockIdx.x] = v;
    }
}

/* -------------------------------- pd kernel ------------------------------ */
/* Per row: ZPD = sum_m exp(-gamma d^2), TPD = sum_m exp(..)*fd, where only
   pairs with d^2 < STH contribute (rest underflow to 0, matching fp32 ref). */
__global__ void __launch_bounds__(1024)
pd_kernel(const float* __restrict__ points,
          const float* __restrict__ f1,
          const float* __restrict__ f2)
{
    extern __shared__ __align__(16) char sm[];
    float* spx = (float*)(sm + PD_PX);
    float* spy = (float*)(sm + PD_PY);
    float* spz = (float*)(sm + PD_PZ);
    float* redz = (float*)(sm + PD_RZ);
    float* redt = (float*)(sm + PD_RT);

    const int tid = threadIdx.x;
    const int b = blockIdx.y;

    /* stage all 4096 batch points as SoA */
    {
        const float* pt = points + (size_t)b * NN * 3;
        for (int i = tid; i < NN * 3; i += 1024) {
            float v = pt[i];
            int idx = i / 3, d = i - 3 * idx;
            float* dst = (d == 0) ? spx : ((d == 1) ? spy : spz);
            dst[idx] = v;
        }
    }
    __syncthreads();

    const int r = tid & 127, s = tid >> 7;       /* 8 column splits */
    const int row = blockIdx.x * 128 + r;
    const int n = b * NN + row;
    const float px = spx[row], py = spy[row], pz = spz[row];
    const ull npx2 = pk2(-px, -px), npy2 = pk2(-py, -py), npz2 = pk2(-pz, -pz);
    const float n1 = g_n1[n];

    float zpd = 0.f, tpd = 0.f;
    const ull* px2 = (const ull*)spx;
    const ull* py2 = (const ull*)spy;
    const ull* pz2 = (const ull*)spz;
    const int j0 = s * 256;                       /* 512 cols per split, 2 at a time */

#pragma unroll 4
    for (int j = 0; j < 256; j++) {
        const int cp = j0 + j;
        ull dx = add2_(px2[cp], npx2);
        ull dy = add2_(py2[cp], npy2);
        ull dz = add2_(pz2[cp], npz2);
        ull s2 = mul2_(dx, dx);
        s2 = fma2_(dy, dy, s2);
        s2 = fma2_(dz, dz, s2);
        float2 sv = upk2(s2);
        if (fminf(sv.x, sv.y) < STH) {
#pragma unroll
            for (int k = 0; k < 2; k++) {
                float sc = k ? sv.y : sv.x;
                if (sc < STH) {
                    const int c = 2 * cp + k;
                    float e = ex2_(sc * NGL2E);
                    const float4* a4 = (const float4*)(f1 + (size_t)n * DD);
                    const float4* b4 = (const float4*)(f2 + ((size_t)(b * NN + c)) * DD);
                    float dot = 0.f;
#pragma unroll
                    for (int q = 0; q < 16; q++) {
                        float4 av = a4[q], bv = b4[q];
                        dot = fmaf(av.x, bv.x, dot);
                        dot = fmaf(av.y, bv.y, dot);
                        dot = fmaf(av.z, bv.z, dot);
                        dot = fmaf(av.w, bv.w, dot);
                    }
                    float fdv = 2.f * dot - n1 - g_n2[b * NN + c];
                    zpd += e;
                    tpd = fmaf(e, fdv, tpd);
                }
            }
        }
    }

    /* combine the 8 splits */
    if (s > 0) { redz[(s - 1) * 128 + r] = zpd; redt[(s - 1) * 128 + r] = tpd; }
    __syncthreads();
    if (s == 0) {
#pragma unroll
        for (int k = 0; k < 7; k++) { zpd += redz[k * 128 + r]; tpd += redt[k * 128 + r]; }
        g_pdz[n] = zpd;
        g_pdt[n] = tpd;
    }
}

/* -------------------------------- ce kernel ------------------------------ */
__global__ void __launch_bounds__(THREADS, 1)
ce_kernel(const float* __restrict__ w)
{
    extern __shared__ char sm[];
    const uint32_t smb = smem_u32(sm);
    const int tid = threadIdx.x;
    const int wid = tid >> 5, lane = tid & 31;
    const int rg = wid & 7;          /* row group */
    const int ch = wid >> 3;         /* column half */
    const int b = blockIdx.y, bx = blockIdx.x;

    /* prologue: A tile + B tile 0 + kv 0 */
    {
        const size_t abase = ((size_t)(b * T_TILES + bx)) * 16384;
        const size_t bbase = ((size_t)(b * T_TILES + 0)) * 16384;
#pragma unroll
        for (int j = 0; j < 2; j++) {
            const uint32_t c16 = (uint32_t)(tid + j * 512) * 16;
            CPA16(smb + OFF_A + c16, g_f1h + abase + c16);
            CPA16(smb + OFF_B + c16, g_f2h + bbase + c16);
        }
        if (tid < 32) {
            const uint32_t c16 = (uint32_t)tid * 16;
            CPA16(smb + OFF_KV + c16,
                  (const char*)(g_kvt + (size_t)(b * T_TILES) * 128) + c16);
        }
        CPA_COMMIT();
    }

    const int q = lane & 3;
    const int kq = lane >> 2;
    const int r0 = rg * 16 + kq;
    const int n0 = bx * ROWS + r0;
    const float rowka = g_rowk[b * NN + n0];
    const float rowkb = g_rowk[b * NN + n0 + 8];

    CPA_WAIT0();
    __syncthreads();

    /* persistent A fragments */
    const int g = lane >> 3, li = lane & 7, gh = g >> 1;
    uint32_t af[4][4];
    {
        const int rA = rg * 16 + (g & 1) * 8 + li;
        const uint32_t ab = smb + OFF_A + rA * 128;
        const int sA = rA & 7;
#pragma unroll
        for (int kc = 0; kc < 4; kc++)
            LDSM4(af[kc], ab + (uint32_t)(((2 * kc + gh) ^ sA) << 4));
    }
    const int rl = (g & 1) * 8 + li;
    const int sB = rl & 7;

    float zfd0 = 0.f, zfd1 = 0.f;

    for (int t = 0; t < T_TILES; t++) {
        const int bf = t & 1;
        if (t + 1 < T_TILES) {
            const int nbf = bf ^ 1;
            const size_t bbase = ((size_t)(b * T_TILES + t + 1)) * 16384;
            const uint32_t dstB = smb + OFF_B + nbf * 16384;
#pragma unroll
            for (int j = 0; j < 2; j++) {
                const uint32_t c16 = (uint32_t)(tid + j * 512) * 16;
                CPA16(dstB + c16, g_f2h + bbase + c16);
            }
            if (tid < 32) {
                const uint32_t c16 = (uint32_t)tid * 16;
                CPA16(smb + OFF_KV + nbf * 512 + c16,
                      (const char*)(g_kvt + (size_t)(b * T_TILES + t + 1) * 128) + c16);
            }
            CPA_COMMIT();
        }

        const float* kvp = (const float*)(sm + OFF_KV + bf * 512);
        const uint32_t bbuf = smb + OFF_B + bf * 16384;

#pragma unroll
        for (int cpl = 0; cpl < 4; cpl++) {
            const int cpg = ch * 4 + cpl;
            uint32_t bfrag[4][4];
            const uint32_t bb = bbuf + cpg * 2048 + rl * 128;
#pragma unroll
            for (int kc = 0; kc < 4; kc++)
                LDSM4(bfrag[kc], bb + (uint32_t)(((2 * kc + gh) ^ sB) << 4));

            float accA[4] = {0.f, 0.f, 0.f, 0.f};
            float accB[4] = {0.f, 0.f, 0.f, 0.f};
#pragma unroll
            for (int kc = 0; kc < 4; kc++) {
                MMA16816(accA, af[kc], bfrag[kc][0], bfrag[kc][2]);
                MMA16816(accB, af[kc], bfrag[kc][1], bfrag[kc][3]);
            }

            const int lc0 = cpg * 16 + 2 * q;
            const int lc1 = lc0 + 8;
            const float2 k0 = *(const float2*)(kvp + lc0);
            const float2 k1 = *(const float2*)(kvp + lc1);

            zfd0 += ex2_(fmaf(accA[0], TWO_L2E, rowka + k0.x));
            zfd0 += ex2_(fmaf(accA[1], TWO_L2E, rowka + k0.y));
            zfd0 += ex2_(fmaf(accB[0], TWO_L2E, rowka + k1.x));
            zfd0 += ex2_(fmaf(accB[1], TWO_L2E, rowka + k1.y));
            zfd1 += ex2_(fmaf(accA[2], TWO_L2E, rowkb + k0.x));
            zfd1 += ex2_(fmaf(accA[3], TWO_L2E, rowkb + k0.y));
            zfd1 += ex2_(fmaf(accB[2], TWO_L2E, rowkb + k1.x));
            zfd1 += ex2_(fmaf(accB[3], TWO_L2E, rowkb + k1.y));
        }

        if (t + 1 < T_TILES) CPA_WAIT0();
        __syncthreads();
    }

    /* reduce quad lanes */
#pragma unroll
    for (int o = 1; o <= 2; o <<= 1) {
        zfd0 += __shfl_xor_sync(0xffffffffu, zfd0, o);
        zfd1 += __shfl_xor_sync(0xffffffffu, zfd1, o);
    }
    /* combine the two column halves via smem */
    float* red = (float*)(sm + OFF_RED);
    if (ch == 1 && q == 0) { red[r0] = zfd0; red[r0 + 8] = zfd1; }
    __syncthreads();
    float val = 0.f;
    if (ch == 0 && q == 0) {
        const float ZF0 = zfd0 + red[r0];
        const float ZF1 = zfd1 + red[r0 + 8];
        const int na = b * NN + n0, nb_ = na + 8;
        const float ce0 = (logf(ZF0) - SHIFT) - g_pdt[na] / g_pdz[na];
        const float ce1 = (logf(ZF1) - SHIFT) - g_pdt[nb_] / g_pdz[nb_];
        val = w[na] * ce0 + w[nb_] * ce1;
    }
#pragma unroll
    for (int o = 16; o >= 4; o >>= 1) val += __shfl_down_sync(0xffffffffu, val, o);
    float* wsum = (float*)(sm + OFF_WSUM);
    if (lane == 0) wsum[wid] = val;
    __syncthreads();
    if (tid < 8) {
        float v = wsum[tid];
        v += __shfl_down_sync(0xffu, v, 4);
        v += __shfl_down_sync(0xffu, v, 2);
        v += __shfl_down_sync(0xffu, v, 1);
        if (tid == 0) g_cep[b * 32 + bx] = v;
    }
}

/* ------------------------------- final kernel ---------------------------- */
__global__ void final_kernel(float* __restrict__ out)
{
    const int tid = threadIdx.x;
    if (tid < 128) {
        float v = g_cep[tid];
#pragma unroll
        for (int o = 16; o > 0; o >>= 1) v += __shfl_down_sync(0xffffffffu, v, o);
        if ((tid & 31) == 0) out[tid >> 5] = v;      /* warp w == batch w */
    } else if (tid < 132) {
        const int bb = tid - 128;
        float s = 0.f;
#pragma unroll
        for (int i = 0; i < 16; i++) s += g_regp[bb * 16 + i];
        out[4 + bb] = s * (1.0f / (float)(NN * DD));
    }
}

/* -------------------------------- launcher ------------------------------- */
extern "C" void kernel_launch(void* const* d_in, const int* in_sizes, int n_in,
                              void* d_out, int out_size)
{
    const float* points = (const float*)d_in[0];
    const float* f1     = (const float*)d_in[1];
    const float* f2     = (const float*)d_in[2];
    const float* w      = (const float*)d_in[3];
    float* out          = (float*)d_out;

    static bool attr_set = false;
    if (!attr_set) {
        cudaFuncSetAttribute(ce_kernel, cudaFuncAttributeMaxDynamicSharedMemorySize, SMEM_CE);
        cudaFuncSetAttribute(pd_kernel, cudaFuncAttributeMaxDynamicSharedMemorySize, SMEM_PD);
        attr_set = true;
    }

    prep_kernel<<<BB * NN / 256, 256>>>(f1, f2);
    pd_kernel<<<dim3(NN / 128, BB), 1024, SMEM_PD>>>(points, f1, f2);
    ce_kernel<<<dim3(NN / ROWS, BB), THREADS, SMEM_CE>>>(w);
    final_kernel<<<1, 160>>>(out);
}

// round 8
// speedup vs baseline: 1.5887x; 1.5887x over previous
#include <cuda_runtime.h>
#include <cuda_fp16.h>
#include <math.h>
#include <stdint.h>

#define BB 4
#define NN 4096
#define DD 64
#define SHIFT 64.0f
#define L2E 1.4426950408889634f
#define LN2 0.6931471805599453f
#define TWO_L2E (2.0f * L2E)
#define NGL2E (-40000.0f * L2E)       /* -(1/sigma^2)*log2(e) */
#define STH 0.00226f                  /* dist^2 beyond which exp underflows */

#define ROWS 128
#define T_TILES 32
#define THREADS 512

/* ---- ce smem layout (bytes) ---- */
#define OFF_A    0                    /* 16384 */
#define OFF_B    16384                /* 2 x 16384 */
#define OFF_COLC 49152                /* 2 x 2048 */
#define OFF_RED  53248                /* 3*128 floats = 1536 */
#define OFF_WSUM 54784                /* 16 floats */
#define SMEM_CE  54848

/* ---- device scratch ---- */
__device__ __align__(16) unsigned char g_f1h[BB * NN * 128];
__device__ __align__(16) unsigned char g_f2h[BB * NN * 128];
__device__ float g_colc[BB * T_TILES * 4 * 128];  /* x,y,z,kv SoA per tile */
__device__ float g_rowk[BB * NN];                 /* L2E*(SHIFT - n1) */
__device__ float g_cep[BB * 32];
__device__ float g_regp[64];
__device__ unsigned int g_ctr = 0;

typedef unsigned long long ull;

/* ------------------------------- asm helpers ----------------------------- */
__device__ __forceinline__ uint32_t smem_u32(const void* p) {
    uint32_t a;
    asm("{ .reg .u64 t; cvta.to.shared.u64 t, %1; cvt.u32.u64 %0, t; }" : "=r"(a) : "l"(p));
    return a;
}
__device__ __forceinline__ float ex2_(float x) {
    float r;
    asm("ex2.approx.ftz.f32 %0, %1;" : "=f"(r) : "f"(x));
    return r;
}
__device__ __forceinline__ ull pk2(float a, float b) {
    ull r;
    asm("mov.b64 %0, {%1, %2};" : "=l"(r) : "f"(a), "f"(b));
    return r;
}
__device__ __forceinline__ float2 upk2(ull v) {
    float x, y;
    asm("mov.b64 {%0, %1}, %2;" : "=f"(x), "=f"(y) : "l"(v));
    return make_float2(x, y);
}
__device__ __forceinline__ ull add2_(ull a, ull b) {
    ull r;
    asm("add.rn.f32x2 %0, %1, %2;" : "=l"(r) : "l"(a), "l"(b));
    return r;
}
__device__ __forceinline__ ull mul2_(ull a, ull b) {
    ull r;
    asm("mul.rn.f32x2 %0, %1, %2;" : "=l"(r) : "l"(a), "l"(b));
    return r;
}
__device__ __forceinline__ ull fma2_(ull a, ull b, ull c) {
    ull r;
    asm("fma.rn.f32x2 %0, %1, %2, %3;" : "=l"(r) : "l"(a), "l"(b), "l"(c));
    return r;
}
#define CPA16(dst, src) \
    asm volatile("cp.async.cg.shared.global [%0], [%1], 16;" :: "r"(dst), "l"(src))
#define CPA_COMMIT() asm volatile("cp.async.commit_group;" ::: "memory")
#define CPA_WAIT0()  asm volatile("cp.async.wait_group 0;" ::: "memory")

#define LDSM4(r, addr) \
    asm volatile("ldmatrix.sync.aligned.m8n8.x4.shared.b16 {%0,%1,%2,%3}, [%4];" \
        : "=r"((r)[0]), "=r"((r)[1]), "=r"((r)[2]), "=r"((r)[3]) : "r"(addr))

#define MMA16816(c, a, b0_, b1_) \
    asm volatile("mma.sync.aligned.m16n8k16.row.col.f32.f16.f16.f32 " \
        "{%0,%1,%2,%3},{%4,%5,%6,%7},{%8,%9},{%0,%1,%2,%3};" \
        : "+f"((c)[0]), "+f"((c)[1]), "+f"((c)[2]), "+f"((c)[3]) \
        : "r"((a)[0]), "r"((a)[1]), "r"((a)[2]), "r"((a)[3]), "r"(b0_), "r"(b1_))

/* ------------------------------- prep kernel ----------------------------- */
__device__ __forceinline__ uint4 cvt8h(const float* f) {
    uint32_t h[4];
#pragma unroll
    for (int i = 0; i < 4; i++) {
        __half2 hh = __floats2half2_rn(f[2 * i], f[2 * i + 1]);
        h[i] = *reinterpret_cast<uint32_t*>(&hh);
    }
    return make_uint4(h[0], h[1], h[2], h[3]);
}

__global__ void __launch_bounds__(256)
prep_kernel(const float* __restrict__ points,
            const float* __restrict__ f1,
            const float* __restrict__ f2)
{
    __shared__ float wsum[8];
    const int tid = threadIdx.x;
    const int row = blockIdx.x * 256 + tid;        /* 0 .. B*NN-1 */
    const int b = row >> 12, n = row & (NN - 1);
    const int t = n >> 7, rin = n & 127;
    const size_t tb = ((size_t)(b * T_TILES + t)) * 16384 + (size_t)rin * 128;
    const int sw = rin & 7;

    float f[DD];
    float n1 = 0.f, n2 = 0.f;
    {
        const float4* v = (const float4*)(f1 + (size_t)row * DD);
#pragma unroll
        for (int j = 0; j < DD / 4; j++) {
            float4 x = v[j];
            f[4 * j] = x.x; f[4 * j + 1] = x.y; f[4 * j + 2] = x.z; f[4 * j + 3] = x.w;
            n1 = fmaf(x.x, x.x, n1); n1 = fmaf(x.y, x.y, n1);
            n1 = fmaf(x.z, x.z, n1); n1 = fmaf(x.w, x.w, n1);
        }
#pragma unroll
        for (int c = 0; c < 8; c++)
            *reinterpret_cast<uint4*>(g_f1h + tb + (size_t)(((c ^ sw) << 4))) = cvt8h(f + 8 * c);
    }
    {
        const float4* v = (const float4*)(f2 + (size_t)row * DD);
#pragma unroll
        for (int j = 0; j < DD / 4; j++) {
            float4 x = v[j];
            f[4 * j] = x.x; f[4 * j + 1] = x.y; f[4 * j + 2] = x.z; f[4 * j + 3] = x.w;
            n2 = fmaf(x.x, x.x, n2); n2 = fmaf(x.y, x.y, n2);
            n2 = fmaf(x.z, x.z, n2); n2 = fmaf(x.w, x.w, n2);
        }
#pragma unroll
        for (int c = 0; c < 8; c++)
            *reinterpret_cast<uint4*>(g_f2h + tb + (size_t)(((c ^ sw) << 4))) = cvt8h(f + 8 * c);
    }
    g_rowk[row] = L2E * (SHIFT - n1);
    const int cbase = (b * T_TILES + t) * 512;
    g_colc[cbase + rin]       = points[(size_t)row * 3 + 0];
    g_colc[cbase + 128 + rin] = points[(size_t)row * 3 + 1];
    g_colc[cbase + 256 + rin] = points[(size_t)row * 3 + 2];
    g_colc[cbase + 384 + rin] = -L2E * n2;

    /* reg loss partial */
    float s = n1 + n2;
#pragma unroll
    for (int o = 16; o > 0; o >>= 1) s += __shfl_down_sync(0xffffffffu, s, o);
    if ((tid & 31) == 0) wsum[tid >> 5] = s;
    __syncthreads();
    if (tid < 8) {
        float v = wsum[tid];
        v += __shfl_down_sync(0xffu, v, 4);
        v += __shfl_down_sync(0xffu, v, 2);
        v += __shfl_down_sync(0xffu, v, 1);
        if (tid == 0) g_regp[blockIdx.x] = v;
    }
}

/* -------------------------------- ce kernel ------------------------------ */
__global__ void __launch_bounds__(THREADS, 1)
ce_kernel(const float* __restrict__ w, float* __restrict__ out)
{
    extern __shared__ char sm[];
    const uint32_t smb = smem_u32(sm);
    const int tid = threadIdx.x;
    const int wid = tid >> 5, lane = tid & 31;
    const int rg = wid & 7;          /* row group */
    const int ch = wid >> 3;         /* column half */
    const int b = blockIdx.y, bx = blockIdx.x;

    /* prologue: A tile + B tile 0 + colc 0 */
    {
        const size_t abase = ((size_t)(b * T_TILES + bx)) * 16384;
        const size_t bbase = ((size_t)(b * T_TILES + 0)) * 16384;
#pragma unroll
        for (int j = 0; j < 2; j++) {
            const uint32_t c16 = (uint32_t)(tid + j * 512) * 16;
            CPA16(smb + OFF_A + c16, g_f1h + abase + c16);
            CPA16(smb + OFF_B + c16, g_f2h + bbase + c16);
        }
        if (tid < 128) {
            const uint32_t c16 = (uint32_t)tid * 16;
            CPA16(smb + OFF_COLC + c16,
                  (const char*)(g_colc + (size_t)(b * T_TILES) * 512) + c16);
        }
        CPA_COMMIT();
    }

    const int q = lane & 3;
    const int kq = lane >> 2;
    const int r0 = rg * 16 + kq;
    const int n0 = bx * ROWS + r0;
    const float rowka = g_rowk[b * NN + n0];
    const float rowkb = g_rowk[b * NN + n0 + 8];
    const ull rowka2 = pk2(rowka, rowka);
    const ull rowkb2 = pk2(rowkb, rowkb);
    const ull TL2E2 = pk2(TWO_L2E, TWO_L2E);

    CPA_WAIT0();
    __syncthreads();

    /* row point coords (colc tile bx holds exactly this CTA's rows) */
    const float* myc = g_colc + (size_t)(b * T_TILES + bx) * 512;
    const float pxa = myc[r0],     pya = myc[128 + r0],     pza = myc[256 + r0];
    const float pxb = myc[r0 + 8], pyb = myc[128 + r0 + 8], pzb = myc[256 + r0 + 8];
    const ull npxa2 = pk2(-pxa, -pxa), npya2 = pk2(-pya, -pya), npza2 = pk2(-pza, -pza);
    const ull npxb2 = pk2(-pxb, -pxb), npyb2 = pk2(-pyb, -pyb), npzb2 = pk2(-pzb, -pzb);

    /* persistent A fragments */
    const int g = lane >> 3, li = lane & 7, gh = g >> 1;
    uint32_t af[4][4];
    {
        const int rA = rg * 16 + (g & 1) * 8 + li;
        const uint32_t ab = smb + OFF_A + rA * 128;
        const int sA = rA & 7;
#pragma unroll
        for (int kc = 0; kc < 4; kc++)
            LDSM4(af[kc], ab + (uint32_t)(((2 * kc + gh) ^ sA) << 4));
    }
    const int rl = (g & 1) * 8 + li;
    const int sB = rl & 7;

    float zpd0 = 0.f, tpd0 = 0.f, zfd0 = 0.f;
    float zpd1 = 0.f, tpd1 = 0.f, zfd1 = 0.f;

    for (int t = 0; t < T_TILES; t++) {
        const int bf = t & 1;
        if (t + 1 < T_TILES) {
            const int nbf = bf ^ 1;
            const size_t bbase = ((size_t)(b * T_TILES + t + 1)) * 16384;
            const uint32_t dstB = smb + OFF_B + nbf * 16384;
#pragma unroll
            for (int j = 0; j < 2; j++) {
                const uint32_t c16 = (uint32_t)(tid + j * 512) * 16;
                CPA16(dstB + c16, g_f2h + bbase + c16);
            }
            if (tid < 128) {
                const uint32_t c16 = (uint32_t)tid * 16;
                CPA16(smb + OFF_COLC + nbf * 2048 + c16,
                      (const char*)(g_colc + (size_t)(b * T_TILES + t + 1) * 512) + c16);
            }
            CPA_COMMIT();
        }

        const float* colcp = (const float*)(sm + OFF_COLC + bf * 2048);
        const uint32_t bbuf = smb + OFF_B + bf * 16384;

#pragma unroll
        for (int cpl = 0; cpl < 4; cpl++) {
            const int cpg = ch * 4 + cpl;
            uint32_t bfrag[4][4];
            const uint32_t bb = bbuf + cpg * 2048 + rl * 128;
#pragma unroll
            for (int kc = 0; kc < 4; kc++)
                LDSM4(bfrag[kc], bb + (uint32_t)(((2 * kc + gh) ^ sB) << 4));

            float accA[4] = {0.f, 0.f, 0.f, 0.f};
            float accB[4] = {0.f, 0.f, 0.f, 0.f};
#pragma unroll
            for (int kc = 0; kc < 4; kc++) {
                MMA16816(accA, af[kc], bfrag[kc][0], bfrag[kc][2]);
                MMA16816(accB, af[kc], bfrag[kc][1], bfrag[kc][3]);
            }

            const int lc0 = cpg * 16 + 2 * q;
            const int lc1 = lc0 + 8;
            const ull qx01 = *(const ull*)(colcp + lc0);
            const ull qx89 = *(const ull*)(colcp + lc1);
            const ull qy01 = *(const ull*)(colcp + 128 + lc0);
            const ull qy89 = *(const ull*)(colcp + 128 + lc1);
            const ull qz01 = *(const ull*)(colcp + 256 + lc0);
            const ull qz89 = *(const ull*)(colcp + 256 + lc1);
            const ull kv01 = *(const ull*)(colcp + 384 + lc0);
            const ull kv89 = *(const ull*)(colcp + 384 + lc1);

            /* feature side: zarg = L2E*(fd + SHIFT), packed per column pair */
            const ull zaa01 = fma2_(pk2(accA[0], accA[1]), TL2E2, add2_(rowka2, kv01));
            const ull zaa89 = fma2_(pk2(accB[0], accB[1]), TL2E2, add2_(rowka2, kv89));
            const ull zab01 = fma2_(pk2(accA[2], accA[3]), TL2E2, add2_(rowkb2, kv01));
            const ull zab89 = fma2_(pk2(accB[2], accB[3]), TL2E2, add2_(rowkb2, kv89));
            const float2 fa01 = upk2(zaa01), fa89 = upk2(zaa89);
            const float2 fb01 = upk2(zab01), fb89 = upk2(zab89);
            zfd0 += ex2_(fa01.x) + ex2_(fa01.y) + ex2_(fa89.x) + ex2_(fa89.y);
            zfd1 += ex2_(fb01.x) + ex2_(fb01.y) + ex2_(fb89.x) + ex2_(fb89.y);

            /* point side, row a: dx^2 prefilter, exact recompute if near */
            {
                const ull dx01 = add2_(qx01, npxa2), dx89 = add2_(qx89, npxa2);
                const float2 x0 = upk2(mul2_(dx01, dx01)), x1 = upk2(mul2_(dx89, dx89));
                if (fminf(fminf(x0.x, x0.y), fminf(x1.x, x1.y)) < STH) {
                    const ull dy01 = add2_(qy01, npya2), dy89 = add2_(qy89, npya2);
                    const ull dz01 = add2_(qz01, npza2), dz89 = add2_(qz89, npza2);
                    const float2 s0 = upk2(fma2_(dz01, dz01, fma2_(dy01, dy01, mul2_(dx01, dx01))));
                    const float2 s1 = upk2(fma2_(dz89, dz89, fma2_(dy89, dy89, mul2_(dx89, dx89))));
                    if (fminf(fminf(s0.x, s0.y), fminf(s1.x, s1.y)) < STH) {
                        float e;
                        e = ex2_(s0.x * NGL2E); zpd0 += e; tpd0 = fmaf(e, fmaf(fa01.x, LN2, -SHIFT), tpd0);
                        e = ex2_(s0.y * NGL2E); zpd0 += e; tpd0 = fmaf(e, fmaf(fa01.y, LN2, -SHIFT), tpd0);
                        e = ex2_(s1.x * NGL2E); zpd0 += e; tpd0 = fmaf(e, fmaf(fa89.x, LN2, -SHIFT), tpd0);
                        e = ex2_(s1.y * NGL2E); zpd0 += e; tpd0 = fmaf(e, fmaf(fa89.y, LN2, -SHIFT), tpd0);
                    }
                }
            }
            /* point side, row b */
            {
                const ull dx01 = add2_(qx01, npxb2), dx89 = add2_(qx89, npxb2);
                const float2 x0 = upk2(mul2_(dx01, dx01)), x1 = upk2(mul2_(dx89, dx89));
                if (fminf(fminf(x0.x, x0.y), fminf(x1.x, x1.y)) < STH) {
                    const ull dy01 = add2_(qy01, npyb2), dy89 = add2_(qy89, npyb2);
                    const ull dz01 = add2_(qz01, npzb2), dz89 = add2_(qz89, npzb2);
                    const float2 s0 = upk2(fma2_(dz01, dz01, fma2_(dy01, dy01, mul2_(dx01, dx01))));
                    const float2 s1 = upk2(fma2_(dz89, dz89, fma2_(dy89, dy89, mul2_(dx89, dx89))));
                    if (fminf(fminf(s0.x, s0.y), fminf(s1.x, s1.y)) < STH) {
                        float e;
                        e = ex2_(s0.x * NGL2E); zpd1 += e; tpd1 = fmaf(e, fmaf(fb01.x, LN2, -SHIFT), tpd1);
                        e = ex2_(s0.y * NGL2E); zpd1 += e; tpd1 = fmaf(e, fmaf(fb01.y, LN2, -SHIFT), tpd1);
                        e = ex2_(s1.x * NGL2E); zpd1 += e; tpd1 = fmaf(e, fmaf(fb89.x, LN2, -SHIFT), tpd1);
                        e = ex2_(s1.y * NGL2E); zpd1 += e; tpd1 = fmaf(e, fmaf(fb89.y, LN2, -SHIFT), tpd1);
                    }
                }
            }
        }

        if (t + 1 < T_TILES) CPA_WAIT0();
        __syncthreads();
    }

    /* reduce quad lanes */
#pragma unroll
    for (int o = 1; o <= 2; o <<= 1) {
        zfd0 += __shfl_xor_sync(0xffffffffu, zfd0, o);
        zpd0 += __shfl_xor_sync(0xffffffffu, zpd0, o);
        tpd0 += __shfl_xor_sync(0xffffffffu, tpd0, o);
        zfd1 += __shfl_xor_sync(0xffffffffu, zfd1, o);
        zpd1 += __shfl_xor_sync(0xffffffffu, zpd1, o);
        tpd1 += __shfl_xor_sync(0xffffffffu, tpd1, o);
    }
    /* combine the two column halves via smem */
    float* red = (float*)(sm + OFF_RED);
    if (ch == 1 && q == 0) {
        red[r0] = zfd0;           red[r0 + 8] = zfd1;
        red[128 + r0] = zpd0;     red[128 + r0 + 8] = zpd1;
        red[256 + r0] = tpd0;     red[256 + r0 + 8] = tpd1;
    }
    __syncthreads();
    float val = 0.f;
    if (ch == 0 && q == 0) {
        const float ZF0 = zfd0 + red[r0];
        const float ZF1 = zfd1 + red[r0 + 8];
        const float ZP0 = zpd0 + red[128 + r0];
        const float ZP1 = zpd1 + red[128 + r0 + 8];
        const float TP0 = tpd0 + red[256 + r0];
        const float TP1 = tpd1 + red[256 + r0 + 8];
        const int na = b * NN + n0, nb_ = na + 8;
        const float ce0 = (logf(ZF0) - SHIFT) - TP0 / ZP0;
        const float ce1 = (logf(ZF1) - SHIFT) - TP1 / ZP1;
        val = w[na] * ce0 + w[nb_] * ce1;
    }
#pragma unroll
    for (int o = 16; o >= 4; o >>= 1) val += __shfl_down_sync(0xffffffffu, val, o);
    float* wsum = (float*)(sm + OFF_WSUM);
    if (lane == 0) wsum[wid] = val;
    __syncthreads();
    if (tid < 8) {
        float v = wsum[tid];
        v += __shfl_down_sync(0xffu, v, 4);
        v += __shfl_down_sync(0xffu, v, 2);
        v += __shfl_down_sync(0xffu, v, 1);
        if (tid == 0) g_cep[b * 32 + bx] = v;
    }

    /* ---- ticket: last CTA writes all 8 outputs ---- */
    __shared__ unsigned int lastTicket;
    __threadfence();
    if (tid == 0) lastTicket = atomicAdd(&g_ctr, 1u);
    __syncthreads();
    if (lastTicket == gridDim.x * gridDim.y - 1) {
        if (tid < 128) {
            float v = g_cep[tid];
#pragma unroll
            for (int o = 16; o > 0; o >>= 1) v += __shfl_down_sync(0xffffffffu, v, o);
            if ((tid & 31) == 0) out[tid >> 5] = v;
        } else if (tid < 192) {
            float v = g_regp[tid - 128];
#pragma unroll
            for (int o = 8; o > 0; o >>= 1) v += __shfl_down_sync(0xffffffffu, v, o, 16);
            if ((tid & 15) == 0) out[4 + ((tid - 128) >> 4)] = v * (1.0f / (float)(NN * DD));
        }
        if (tid == 0) g_ctr = 0;
    }
}

/* -------------------------------- launcher ------------------------------- */
extern "C" void kernel_launch(void* const* d_in, const int* in_sizes, int n_in,
                              void* d_out, int out_size)
{
    const float* points = (const float*)d_in[0];
    const float* f1     = (const float*)d_in[1];
    const float* f2     = (const float*)d_in[2];
    const float* w      = (const float*)d_in[3];
    float* out          = (float*)d_out;

    static bool attr_set = false;
    if (!attr_set) {
        cudaFuncSetAttribute(ce_kernel, cudaFuncAttributeMaxDynamicSharedMemorySize, SMEM_CE);
        attr_set = true;
    }

    prep_kernel<<<BB * NN / 256, 256>>>(points, f1, f2);
    ce_kernel<<<dim3(NN / ROWS, BB), THREADS, SMEM_CE>>>(w, out);
}

// round 9
// speedup vs baseline: 1.6933x; 1.0658x over previous
#include <cuda_runtime.h>
#include <cuda_fp16.h>
#include <math.h>
#include <stdint.h>

#define BB 4
#define NN 4096
#define DD 64
#define SHIFT 64.0f
#define L2E 1.4426950408889634f
#define LN2 0.6931471805599453f
#define TWO_L2E (2.0f * L2E)
#define NGL2E (-40000.0f * L2E)       /* -(1/sigma^2)*log2(e) */
#define STH 0.00226f                  /* dist^2 beyond which exp underflows */

#define ROWS 64                       /* rows per CTA */
#define T_TILES 32                    /* column tiles of 128 */
#define THREADS 256
#define NCTA (BB * NN / ROWS)         /* 256 */

/* ---- ce smem layout (bytes) ---- */
#define OFF_A    0                    /* 8192 */
#define OFF_B    8192                 /* 2 x 16384 */
#define OFF_COLC 40960                /* 2 x 2048 */
#define OFF_RED  45056                /* 3*64 floats = 768 */
#define OFF_WSUM 45824                /* 8 floats */
#define SMEM_CE  45888

/* ---- device scratch ---- */
__device__ __align__(16) unsigned char g_f1h[BB * NN * 128];
__device__ __align__(16) unsigned char g_f2h[BB * NN * 128];
__device__ float g_colc[BB * T_TILES * 4 * 128];  /* x,y,z,kv SoA per 128-col tile */
__device__ float g_rowk[BB * NN];                 /* L2E*(SHIFT - n1) */
__device__ float g_cep[BB * 64];
__device__ float g_regp[64];
__device__ unsigned int g_ctr = 0;

/* ------------------------------- asm helpers ----------------------------- */
__device__ __forceinline__ uint32_t smem_u32(const void* p) {
    uint32_t a;
    asm("{ .reg .u64 t; cvta.to.shared.u64 t, %1; cvt.u32.u64 %0, t; }" : "=r"(a) : "l"(p));
    return a;
}
__device__ __forceinline__ float ex2_(float x) {
    float r;
    asm("ex2.approx.ftz.f32 %0, %1;" : "=f"(r) : "f"(x));
    return r;
}
#define CPA16(dst, src) \
    asm volatile("cp.async.cg.shared.global [%0], [%1], 16;" :: "r"(dst), "l"(src))
#define CPA_COMMIT() asm volatile("cp.async.commit_group;" ::: "memory")
#define CPA_WAIT0()  asm volatile("cp.async.wait_group 0;" ::: "memory")

#define LDSM4(r, addr) \
    asm volatile("ldmatrix.sync.aligned.m8n8.x4.shared.b16 {%0,%1,%2,%3}, [%4];" \
        : "=r"((r)[0]), "=r"((r)[1]), "=r"((r)[2]), "=r"((r)[3]) : "r"(addr))

#define MMA16816(c, a, b0_, b1_) \
    asm volatile("mma.sync.aligned.m16n8k16.row.col.f32.f16.f16.f32 " \
        "{%0,%1,%2,%3},{%4,%5,%6,%7},{%8,%9},{%0,%1,%2,%3};" \
        : "+f"((c)[0]), "+f"((c)[1]), "+f"((c)[2]), "+f"((c)[3]) \
        : "r"((a)[0]), "r"((a)[1]), "r"((a)[2]), "r"((a)[3]), "r"(b0_), "r"(b1_))

/* ------------------------------- prep kernel ----------------------------- */
__device__ __forceinline__ uint4 cvt8h(const float* f) {
    uint32_t h[4];
#pragma unroll
    for (int i = 0; i < 4; i++) {
        __half2 hh = __floats2half2_rn(f[2 * i], f[2 * i + 1]);
        h[i] = *reinterpret_cast<uint32_t*>(&hh);
    }
    return make_uint4(h[0], h[1], h[2], h[3]);
}

__global__ void __launch_bounds__(256)
prep_kernel(const float* __restrict__ points,
            const float* __restrict__ f1,
            const float* __restrict__ f2)
{
    __shared__ float wsum[8];
    const int tid = threadIdx.x;
    const int row = blockIdx.x * 256 + tid;        /* 0 .. B*NN-1 */
    const int b = row >> 12, n = row & (NN - 1);
    const int t = n >> 7, rin = n & 127;
    const size_t tb = ((size_t)(b * T_TILES + t)) * 16384 + (size_t)rin * 128;
    const int sw = rin & 7;

    float f[DD];
    float n1 = 0.f, n2 = 0.f;
    {
        const float4* v = (const float4*)(f1 + (size_t)row * DD);
#pragma unroll
        for (int j = 0; j < DD / 4; j++) {
            float4 x = v[j];
            f[4 * j] = x.x; f[4 * j + 1] = x.y; f[4 * j + 2] = x.z; f[4 * j + 3] = x.w;
            n1 = fmaf(x.x, x.x, n1); n1 = fmaf(x.y, x.y, n1);
            n1 = fmaf(x.z, x.z, n1); n1 = fmaf(x.w, x.w, n1);
        }
#pragma unroll
        for (int c = 0; c < 8; c++)
            *reinterpret_cast<uint4*>(g_f1h + tb + (size_t)(((c ^ sw) << 4))) = cvt8h(f + 8 * c);
    }
    {
        const float4* v = (const float4*)(f2 + (size_t)row * DD);
#pragma unroll
        for (int j = 0; j < DD / 4; j++) {
            float4 x = v[j];
            f[4 * j] = x.x; f[4 * j + 1] = x.y; f[4 * j + 2] = x.z; f[4 * j + 3] = x.w;
            n2 = fmaf(x.x, x.x, n2); n2 = fmaf(x.y, x.y, n2);
            n2 = fmaf(x.z, x.z, n2); n2 = fmaf(x.w, x.w, n2);
        }
#pragma unroll
        for (int c = 0; c < 8; c++)
            *reinterpret_cast<uint4*>(g_f2h + tb + (size_t)(((c ^ sw) << 4))) = cvt8h(f + 8 * c);
    }
    g_rowk[row] = L2E * (SHIFT - n1);
    const int cbase = (b * T_TILES + t) * 512;
    g_colc[cbase + rin]       = points[(size_t)row * 3 + 0];
    g_colc[cbase + 128 + rin] = points[(size_t)row * 3 + 1];
    g_colc[cbase + 256 + rin] = points[(size_t)row * 3 + 2];
    g_colc[cbase + 384 + rin] = -L2E * n2;

    /* reg loss partial */
    float s = n1 + n2;
#pragma unroll
    for (int o = 16; o > 0; o >>= 1) s += __shfl_down_sync(0xffffffffu, s, o);
    if ((tid & 31) == 0) wsum[tid >> 5] = s;
    __syncthreads();
    if (tid < 8) {
        float v = wsum[tid];
        v += __shfl_down_sync(0xffu, v, 4);
        v += __shfl_down_sync(0xffu, v, 2);
        v += __shfl_down_sync(0xffu, v, 1);
        if (tid == 0) g_regp[blockIdx.x] = v;
    }
}

/* ----------------------------- epilogue helper --------------------------- */
__device__ __forceinline__ void row_epi(
    float d0, float d1, float d2, float d3,
    const float* qxv, const float* qyv, const float* qzv, const float* kv,
    float px, float py, float pz, float rowk,
    float& zpd, float& tpd, float& zfd)
{
    float dv[4] = { d0, d1, d2, d3 };
    float za[4], sv[4];
    float smin = 1e30f;
#pragma unroll
    for (int c = 0; c < 4; c++) {
        float dx = qxv[c] - px, dy = qyv[c] - py, dz = qzv[c] - pz;
        float s = fmaf(dx, dx, fmaf(dy, dy, dz * dz));
        sv[c] = s;
        smin = fminf(smin, s);
        float zarg = fmaf(dv[c], TWO_L2E, rowk + kv[c]);  /* = L2E*(fd+SHIFT) */
        za[c] = zarg;
        zfd += ex2_(zarg);
    }
    if (smin < STH) {
#pragma unroll
        for (int c = 0; c < 4; c++) {
            float e = ex2_(sv[c] * NGL2E);
            zpd += e;
            float fd = fmaf(za[c], LN2, -SHIFT);
            tpd = fmaf(e, fd, tpd);
        }
    }
}

/* -------------------------------- ce kernel ------------------------------ */
__global__ void __launch_bounds__(THREADS, 2)
ce_kernel(const float* __restrict__ points,
          const float* __restrict__ w,
          float* __restrict__ out)
{
    extern __shared__ char sm[];
    const uint32_t smb = smem_u32(sm);
    const int tid = threadIdx.x;
    const int wid = tid >> 5, lane = tid & 31;
    const int rg = wid & 3;          /* row group (16 rows) */
    const int ch = wid >> 2;         /* column half */
    const int b = blockIdx.y, bx = blockIdx.x;

    /* prologue: A slice (64 rows) + B tile 0 + colc 0 */
    {
        const size_t abase = ((size_t)(b * T_TILES + (bx >> 1))) * 16384
                           + (size_t)(bx & 1) * 64 * 128;
        const size_t bbase = ((size_t)(b * T_TILES + 0)) * 16384;
#pragma unroll
        for (int j = 0; j < 2; j++) {
            const uint32_t c16 = (uint32_t)(tid + j * 256) * 16;
            CPA16(smb + OFF_A + c16, g_f1h + abase + c16);
        }
#pragma unroll
        for (int j = 0; j < 4; j++) {
            const uint32_t c16 = (uint32_t)(tid + j * 256) * 16;
            CPA16(smb + OFF_B + c16, g_f2h + bbase + c16);
        }
        if (tid < 128) {
            const uint32_t c16 = (uint32_t)tid * 16;
            CPA16(smb + OFF_COLC + c16,
                  (const char*)(g_colc + (size_t)(b * T_TILES) * 512) + c16);
        }
        CPA_COMMIT();
    }

    const int q = lane & 3;
    const int kq = lane >> 2;
    const int r0 = rg * 16 + kq;
    const int n0 = bx * ROWS + r0;
    const float rowka = g_rowk[b * NN + n0];
    const float rowkb = g_rowk[b * NN + n0 + 8];
    const float pxa = points[((size_t)(b * NN + n0)) * 3 + 0];
    const float pya = points[((size_t)(b * NN + n0)) * 3 + 1];
    const float pza = points[((size_t)(b * NN + n0)) * 3 + 2];
    const float pxb = points[((size_t)(b * NN + n0 + 8)) * 3 + 0];
    const float pyb = points[((size_t)(b * NN + n0 + 8)) * 3 + 1];
    const float pzb = points[((size_t)(b * NN + n0 + 8)) * 3 + 2];

    CPA_WAIT0();
    __syncthreads();

    /* persistent A fragments (16 rows x 64 k) */
    const int g = lane >> 3, li = lane & 7, gh = g >> 1;
    uint32_t af[4][4];
    {
        const int rA = rg * 16 + (g & 1) * 8 + li;
        const uint32_t ab = smb + OFF_A + rA * 128;
        const int sA = rA & 7;
#pragma unroll
        for (int kc = 0; kc < 4; kc++)
            LDSM4(af[kc], ab + (uint32_t)(((2 * kc + gh) ^ sA) << 4));
    }
    const int rl = (g & 1) * 8 + li;
    const int sB = rl & 7;

    float zpd0 = 0.f, tpd0 = 0.f, zfd0 = 0.f;
    float zpd1 = 0.f, tpd1 = 0.f, zfd1 = 0.f;

    for (int t = 0; t < T_TILES; t++) {
        const int bf = t & 1;
        if (t + 1 < T_TILES) {
            const int nbf = bf ^ 1;
            const size_t bbase = ((size_t)(b * T_TILES + t + 1)) * 16384;
            const uint32_t dstB = smb + OFF_B + nbf * 16384;
#pragma unroll
            for (int j = 0; j < 4; j++) {
                const uint32_t c16 = (uint32_t)(tid + j * 256) * 16;
                CPA16(dstB + c16, g_f2h + bbase + c16);
            }
            if (tid < 128) {
                const uint32_t c16 = (uint32_t)tid * 16;
                CPA16(smb + OFF_COLC + nbf * 2048 + c16,
                      (const char*)(g_colc + (size_t)(b * T_TILES + t + 1) * 512) + c16);
            }
            CPA_COMMIT();
        }

        const float* colcp = (const float*)(sm + OFF_COLC + bf * 2048);
        const uint32_t bbuf = smb + OFF_B + bf * 16384;

#pragma unroll
        for (int cpl = 0; cpl < 4; cpl++) {
            const int cpg = ch * 4 + cpl;          /* 16-col group index */
            uint32_t bfrag[4][4];
            const uint32_t bb = bbuf + cpg * 2048 + rl * 128;
#pragma unroll
            for (int kc = 0; kc < 4; kc++)
                LDSM4(bfrag[kc], bb + (uint32_t)(((2 * kc + gh) ^ sB) << 4));

            float accA[4] = {0.f, 0.f, 0.f, 0.f};
            float accB[4] = {0.f, 0.f, 0.f, 0.f};
#pragma unroll
            for (int kc = 0; kc < 4; kc++) {
                MMA16816(accA, af[kc], bfrag[kc][0], bfrag[kc][2]);
                MMA16816(accB, af[kc], bfrag[kc][1], bfrag[kc][3]);
            }

            const int lc0 = cpg * 16 + 2 * q;
            const int lc1 = lc0 + 8;
            float2 x0 = *(const float2*)(colcp + lc0);
            float2 x1 = *(const float2*)(colcp + lc1);
            float2 y0 = *(const float2*)(colcp + 128 + lc0);
            float2 y1 = *(const float2*)(colcp + 128 + lc1);
            float2 z0 = *(const float2*)(colcp + 256 + lc0);
            float2 z1 = *(const float2*)(colcp + 256 + lc1);
            float2 k0 = *(const float2*)(colcp + 384 + lc0);
            float2 k1 = *(const float2*)(colcp + 384 + lc1);
            const float qxv[4] = { x0.x, x0.y, x1.x, x1.y };
            const float qyv[4] = { y0.x, y0.y, y1.x, y1.y };
            const float qzv[4] = { z0.x, z0.y, z1.x, z1.y };
            const float kv[4]  = { k0.x, k0.y, k1.x, k1.y };

            row_epi(accA[0], accA[1], accB[0], accB[1],
                    qxv, qyv, qzv, kv, pxa, pya, pza, rowka, zpd0, tpd0, zfd0);
            row_epi(accA[2], accA[3], accB[2], accB[3],
                    qxv, qyv, qzv, kv, pxb, pyb, pzb, rowkb, zpd1, tpd1, zfd1);
        }

        if (t + 1 < T_TILES) CPA_WAIT0();
        __syncthreads();
    }

    /* reduce quad lanes */
#pragma unroll
    for (int o = 1; o <= 2; o <<= 1) {
        zfd0 += __shfl_xor_sync(0xffffffffu, zfd0, o);
        zpd0 += __shfl_xor_sync(0xffffffffu, zpd0, o);
        tpd0 += __shfl_xor_sync(0xffffffffu, tpd0, o);
        zfd1 += __shfl_xor_sync(0xffffffffu, zfd1, o);
        zpd1 += __shfl_xor_sync(0xffffffffu, zpd1, o);
        tpd1 += __shfl_xor_sync(0xffffffffu, tpd1, o);
    }
    /* combine the two column halves via smem */
    float* red = (float*)(sm + OFF_RED);
    if (ch == 1 && q == 0) {
        red[r0] = zfd0;          red[r0 + 8] = zfd1;
        red[64 + r0] = zpd0;     red[64 + r0 + 8] = zpd1;
        red[128 + r0] = tpd0;    red[128 + r0 + 8] = tpd1;
    }
    __syncthreads();
    float val = 0.f;
    if (ch == 0 && q == 0) {
        const float ZF0 = zfd0 + red[r0];
        const float ZF1 = zfd1 + red[r0 + 8];
        const float ZP0 = zpd0 + red[64 + r0];
        const float ZP1 = zpd1 + red[64 + r0 + 8];
        const float TP0 = tpd0 + red[128 + r0];
        const float TP1 = tpd1 + red[128 + r0 + 8];
        const int na = b * NN + n0, nb_ = na + 8;
        const float ce0 = (logf(ZF0) - SHIFT) - TP0 / ZP0;
        const float ce1 = (logf(ZF1) - SHIFT) - TP1 / ZP1;
        val = w[na] * ce0 + w[nb_] * ce1;
    }
#pragma unroll
    for (int o = 16; o >= 4; o >>= 1) val += __shfl_down_sync(0xffffffffu, val, o);
    float* wsum = (float*)(sm + OFF_WSUM);
    if (lane == 0) wsum[wid] = val;
    __syncthreads();
    if (tid < 4) {                                /* warps 0-3 are ch==0 */
        float v = wsum[tid];
        v += __shfl_down_sync(0xfu, v, 2);
        v += __shfl_down_sync(0xfu, v, 1);
        if (tid == 0) g_cep[b * 64 + bx] = v;
    }

    /* ---- ticket: last CTA writes all 8 outputs ---- */
    __shared__ unsigned int lastTicket;
    __threadfence();
    if (tid == 0) lastTicket = atomicAdd(&g_ctr, 1u);
    __syncthreads();
    if (lastTicket == NCTA - 1) {
        __threadfence();
        float v = g_cep[tid];                     /* 256 entries, 64 per batch */
#pragma unroll
        for (int o = 16; o > 0; o >>= 1) v += __shfl_down_sync(0xffffffffu, v, o);
        if (lane == 0) wsum[wid] = v;             /* 8 partials, 2 per batch */
        __syncthreads();
        if (tid < 4) out[tid] = wsum[2 * tid] + wsum[2 * tid + 1];
        if (tid >= 32 && tid < 96) {
            const int i = tid - 32;
            float r = g_regp[i];
#pragma unroll
            for (int o = 8; o > 0; o >>= 1) r += __shfl_down_sync(0xffffffffu, r, o, 16);
            if ((i & 15) == 0) out[4 + (i >> 4)] = r * (1.0f / (float)(NN * DD));
        }
        if (tid == 0) g_ctr = 0;
    }
}

/* -------------------------------- launcher ------------------------------- */
extern "C" void kernel_launch(void* const* d_in, const int* in_sizes, int n_in,
                              void* d_out, int out_size)
{
    const float* points = (const float*)d_in[0];
    const float* f1     = (const float*)d_in[1];
    const float* f2     = (const float*)d_in[2];
    const float* w      = (const float*)d_in[3];
    float* out          = (float*)d_out;

    static bool attr_set = false;
    if (!attr_set) {
        cudaFuncSetAttribute(ce_kernel, cudaFuncAttributeMaxDynamicSharedMemorySize, SMEM_CE);
        attr_set = true;
    }

    prep_kernel<<<BB * NN / 256, 256>>>(points, f1, f2);
    ce_kernel<<<dim3(NN / ROWS, BB), THREADS, SMEM_CE>>>(points, w, out);
}

// round 10
// speedup vs baseline: 1.7481x; 1.0324x over previous
#include <cuda_runtime.h>
#include <cuda_fp16.h>
#include <math.h>
#include <stdint.h>

#define BB 4
#define NN 4096
#define DD 64
#define SHIFT 64.0f
#define L2E 1.4426950408889634f
#define LN2 0.6931471805599453f
#define TWO_L2E (2.0f * L2E)
#define TWOGL2E (80000.0f * L2E)      /* 2*gamma*log2(e); zargp = acc * this */
#define STH 0.00226f
#define PDTH (-0.00113f)              /* -STH/2 : acc = -d^2/2 threshold */

#define ROWS 64                       /* rows per CTA */
#define T_TILES 32
#define THREADS 256
#define NCTA (BB * NN / ROWS)         /* 256 */

/* ---- ce smem layout (bytes) ---- */
#define OFF_A    0                    /* 8192 */
#define OFF_B    8192                 /* 2 x 16384 */
#define OFF_COLC 40960                /* 2 x 2048 */
#define OFF_RED  45056                /* 3*64 floats */
#define OFF_WSUM 45824                /* 8 floats */
#define SMEM_CE  45888

/* ---- device scratch ---- */
__device__ __align__(16) unsigned char g_f1h[BB * NN * 128];
__device__ __align__(16) unsigned char g_f2h[BB * NN * 128];
/* per 128-col tile, 512 floats: [0:128) kv  [128:256) pdk=-|p^|^2/2  [256:512) pdh fp16 xyz0 (uint2) */
__device__ float g_colc[BB * T_TILES * 512];
__device__ float g_rowk[BB * NN];     /* L2E*(SHIFT - n1) */
__device__ float g_cep[BB * 64];
__device__ float g_regp[64];
__device__ unsigned int g_ctr = 0;

/* ------------------------------- asm helpers ----------------------------- */
__device__ __forceinline__ uint32_t smem_u32(const void* p) {
    uint32_t a;
    asm("{ .reg .u64 t; cvta.to.shared.u64 t, %1; cvt.u32.u64 %0, t; }" : "=r"(a) : "l"(p));
    return a;
}
__device__ __forceinline__ float ex2_(float x) {
    float r;
    asm("ex2.approx.ftz.f32 %0, %1;" : "=f"(r) : "f"(x));
    return r;
}
#define CPA16(dst, src) \
    asm volatile("cp.async.cg.shared.global [%0], [%1], 16;" :: "r"(dst), "l"(src))
#define CPA_COMMIT() asm volatile("cp.async.commit_group;" ::: "memory")
#define CPA_WAIT0()  asm volatile("cp.async.wait_group 0;" ::: "memory")

#define LDSM4(r, addr) \
    asm volatile("ldmatrix.sync.aligned.m8n8.x4.shared.b16 {%0,%1,%2,%3}, [%4];" \
        : "=r"((r)[0]), "=r"((r)[1]), "=r"((r)[2]), "=r"((r)[3]) : "r"(addr))

#define MMA16816(c, a, b0_, b1_) \
    asm volatile("mma.sync.aligned.m16n8k16.row.col.f32.f16.f16.f32 " \
        "{%0,%1,%2,%3},{%4,%5,%6,%7},{%8,%9},{%0,%1,%2,%3};" \
        : "+f"((c)[0]), "+f"((c)[1]), "+f"((c)[2]), "+f"((c)[3]) \
        : "r"((a)[0]), "r"((a)[1]), "r"((a)[2]), "r"((a)[3]), "r"(b0_), "r"(b1_))

#define MMA1688(c, a0_, a1_, b_) \
    asm volatile("mma.sync.aligned.m16n8k8.row.col.f32.f16.f16.f32 " \
        "{%0,%1,%2,%3},{%4,%5},{%6},{%0,%1,%2,%3};" \
        : "+f"((c)[0]), "+f"((c)[1]), "+f"((c)[2]), "+f"((c)[3]) \
        : "r"(a0_), "r"(a1_), "r"(b_))

/* ------------------------------- prep kernel ----------------------------- */
__device__ __forceinline__ uint4 cvt8h(const float* f) {
    uint32_t h[4];
#pragma unroll
    for (int i = 0; i < 4; i++) {
        __half2 hh = __floats2half2_rn(f[2 * i], f[2 * i + 1]);
        h[i] = *reinterpret_cast<uint32_t*>(&hh);
    }
    return make_uint4(h[0], h[1], h[2], h[3]);
}

__global__ void __launch_bounds__(256)
prep_kernel(const float* __restrict__ points,
            const float* __restrict__ f1,
            const float* __restrict__ f2)
{
    __shared__ float wsum[8];
    const int tid = threadIdx.x;
    const int row = blockIdx.x * 256 + tid;
    const int b = row >> 12, n = row & (NN - 1);
    const int t = n >> 7, rin = n & 127;
    const size_t tb = ((size_t)(b * T_TILES + t)) * 16384 + (size_t)rin * 128;
    const int sw = rin & 7;

    float f[DD];
    float n1 = 0.f, n2 = 0.f;
    {
        const float4* v = (const float4*)(f1 + (size_t)row * DD);
#pragma unroll
        for (int j = 0; j < DD / 4; j++) {
            float4 x = v[j];
            f[4 * j] = x.x; f[4 * j + 1] = x.y; f[4 * j + 2] = x.z; f[4 * j + 3] = x.w;
            n1 = fmaf(x.x, x.x, n1); n1 = fmaf(x.y, x.y, n1);
            n1 = fmaf(x.z, x.z, n1); n1 = fmaf(x.w, x.w, n1);
        }
#pragma unroll
        for (int c = 0; c < 8; c++)
            *reinterpret_cast<uint4*>(g_f1h + tb + (size_t)(((c ^ sw) << 4))) = cvt8h(f + 8 * c);
    }
    {
        const float4* v = (const float4*)(f2 + (size_t)row * DD);
#pragma unroll
        for (int j = 0; j < DD / 4; j++) {
            float4 x = v[j];
            f[4 * j] = x.x; f[4 * j + 1] = x.y; f[4 * j + 2] = x.z; f[4 * j + 3] = x.w;
            n2 = fmaf(x.x, x.x, n2); n2 = fmaf(x.y, x.y, n2);
            n2 = fmaf(x.z, x.z, n2); n2 = fmaf(x.w, x.w, n2);
        }
#pragma unroll
        for (int c = 0; c < 8; c++)
            *reinterpret_cast<uint4*>(g_f2h + tb + (size_t)(((c ^ sw) << 4))) = cvt8h(f + 8 * c);
    }
    g_rowk[row] = L2E * (SHIFT - n1);

    /* fp16-rounded point coords + their norm (consistency: norm FROM rounded) */
    const float px = points[(size_t)row * 3 + 0];
    const float py = points[(size_t)row * 3 + 1];
    const float pz = points[(size_t)row * 3 + 2];
    __half2 hxy = __floats2half2_rn(px, py);
    __half2 hz0 = __floats2half2_rn(pz, 0.f);
    const float xf = __half2float(__low2half(hxy));
    const float yf = __half2float(__high2half(hxy));
    const float zf = __half2float(__low2half(hz0));
    const float np = fmaf(xf, xf, fmaf(yf, yf, zf * zf));

    const int cb = (b * T_TILES + t) * 512;
    g_colc[cb + rin]       = -L2E * n2;            /* kv */
    g_colc[cb + 128 + rin] = -0.5f * np;           /* pdk */
    uint2 wp;
    wp.x = *reinterpret_cast<uint32_t*>(&hxy);
    wp.y = *reinterpret_cast<uint32_t*>(&hz0);
    reinterpret_cast<uint2*>(g_colc + cb + 256)[rin] = wp;

    /* reg loss partial */
    float s = n1 + n2;
#pragma unroll
    for (int o = 16; o > 0; o >>= 1) s += __shfl_down_sync(0xffffffffu, s, o);
    if ((tid & 31) == 0) wsum[tid >> 5] = s;
    __syncthreads();
    if (tid < 8) {
        float v = wsum[tid];
        v += __shfl_down_sync(0xffu, v, 4);
        v += __shfl_down_sync(0xffu, v, 2);
        v += __shfl_down_sync(0xffu, v, 1);
        if (tid == 0) g_regp[blockIdx.x] = v;
    }
}

/* -------------------------------- ce kernel ------------------------------ */
__global__ void __launch_bounds__(THREADS, 2)
ce_kernel(const float* __restrict__ w, float* __restrict__ out)
{
    extern __shared__ char sm[];
    const uint32_t smb = smem_u32(sm);
    const int tid = threadIdx.x;
    const int wid = tid >> 5, lane = tid & 31;
    const int rg = wid & 3;          /* row group (16 rows) */
    const int ch = wid >> 2;         /* column half */
    const int b = blockIdx.y, bx = blockIdx.x;

    /* prologue: A slice (64 rows) + B tile 0 + colc 0 */
    {
        const size_t abase = ((size_t)(b * T_TILES + (bx >> 1))) * 16384
                           + (size_t)(bx & 1) * 64 * 128;
        const size_t bbase = ((size_t)(b * T_TILES + 0)) * 16384;
#pragma unroll
        for (int j = 0; j < 2; j++) {
            const uint32_t c16 = (uint32_t)(tid + j * 256) * 16;
            CPA16(smb + OFF_A + c16, g_f1h + abase + c16);
        }
#pragma unroll
        for (int j = 0; j < 4; j++) {
            const uint32_t c16 = (uint32_t)(tid + j * 256) * 16;
            CPA16(smb + OFF_B + c16, g_f2h + bbase + c16);
        }
        if (tid < 128) {
            const uint32_t c16 = (uint32_t)tid * 16;
            CPA16(smb + OFF_COLC + c16,
                  (const char*)(g_colc + (size_t)(b * T_TILES) * 512) + c16);
        }
        CPA_COMMIT();
    }

    const int q = lane & 3;
    const int kq = lane >> 2;
    const int r0 = rg * 16 + kq;
    const int n0 = bx * ROWS + r0;
    const float rowka = g_rowk[b * NN + n0];
    const float rowkb = g_rowk[b * NN + n0 + 8];

    /* pd row constants + A fragment (fp16 coords of this CTA's rows) */
    const float* mycol = g_colc + (size_t)(b * T_TILES + (bx >> 1)) * 512;
    const int rowoff = (bx & 1) * 64;
    const float prow2a = mycol[128 + rowoff + r0];
    const float prow2b = mycol[128 + rowoff + r0 + 8];
    const uint2* pdh_my = reinterpret_cast<const uint2*>(mycol + 256) + rowoff;
    const int sel = lane & 3;
    uint32_t apd0, apd1;
    {
        uint2 wa0 = pdh_my[rg * 16 + kq];
        uint2 wa1 = pdh_my[rg * 16 + kq + 8];
        apd0 = (sel == 0) ? wa0.x : ((sel == 1) ? wa0.y : 0u);
        apd1 = (sel == 0) ? wa1.x : ((sel == 1) ? wa1.y : 0u);
    }

    CPA_WAIT0();
    __syncthreads();

    /* persistent feature A fragments (16 rows x 64 k) */
    const int g = lane >> 3, li = lane & 7, gh = g >> 1;
    uint32_t af[4][4];
    {
        const int rA = rg * 16 + (g & 1) * 8 + li;
        const uint32_t ab = smb + OFF_A + rA * 128;
        const int sA = rA & 7;
#pragma unroll
        for (int kc = 0; kc < 4; kc++)
            LDSM4(af[kc], ab + (uint32_t)(((2 * kc + gh) ^ sA) << 4));
    }
    const int rl = (g & 1) * 8 + li;
    const int sB = rl & 7;

    float zpd0 = 0.f, tz0 = 0.f, zfd0 = 0.f;
    float zpd1 = 0.f, tz1 = 0.f, zfd1 = 0.f;

    for (int t = 0; t < T_TILES; t++) {
        const int bf = t & 1;
        if (t + 1 < T_TILES) {
            const int nbf = bf ^ 1;
            const size_t bbase = ((size_t)(b * T_TILES + t + 1)) * 16384;
            const uint32_t dstB = smb + OFF_B + nbf * 16384;
#pragma unroll
            for (int j = 0; j < 4; j++) {
                const uint32_t c16 = (uint32_t)(tid + j * 256) * 16;
                CPA16(dstB + c16, g_f2h + bbase + c16);
            }
            if (tid < 128) {
                const uint32_t c16 = (uint32_t)tid * 16;
                CPA16(smb + OFF_COLC + nbf * 2048 + c16,
                      (const char*)(g_colc + (size_t)(b * T_TILES + t + 1) * 512) + c16);
            }
            CPA_COMMIT();
        }

        const float* colcp = (const float*)(sm + OFF_COLC + bf * 2048);
        const float* pdkp = colcp + 128;
        const uint2* pdhp = reinterpret_cast<const uint2*>(colcp + 256);
        const uint32_t bbuf = smb + OFF_B + bf * 16384;

#pragma unroll
        for (int cpl = 0; cpl < 4; cpl++) {
            const int cpg = ch * 4 + cpl;          /* 16-col group index */
            uint32_t bfrag[4][4];
            const uint32_t bb = bbuf + cpg * 2048 + rl * 128;
#pragma unroll
            for (int kc = 0; kc < 4; kc++)
                LDSM4(bfrag[kc], bb + (uint32_t)(((2 * kc + gh) ^ sB) << 4));

            float accA[4] = {0.f, 0.f, 0.f, 0.f};
            float accB[4] = {0.f, 0.f, 0.f, 0.f};
#pragma unroll
            for (int kc = 0; kc < 4; kc++) {
                MMA16816(accA, af[kc], bfrag[kc][0], bfrag[kc][2]);
                MMA16816(accB, af[kc], bfrag[kc][1], bfrag[kc][3]);
            }

            const int lc0 = cpg * 16 + 2 * q;
            const int lc1 = lc0 + 8;

            /* ---- pd MMAs (K=8, coords) ---- */
            uint32_t bpd0, bpd1;
            {
                const int cb0 = cpg * 16 + kq;
                uint2 wb0 = pdhp[cb0];
                uint2 wb1 = pdhp[cb0 + 8];
                bpd0 = (sel == 0) ? wb0.x : ((sel == 1) ? wb0.y : 0u);
                bpd1 = (sel == 0) ? wb1.x : ((sel == 1) ? wb1.y : 0u);
            }
            const float2 pk0 = *(const float2*)(pdkp + lc0);
            const float2 pk1 = *(const float2*)(pdkp + lc1);
            float accP0[4] = { prow2a + pk0.x, prow2a + pk0.y,
                               prow2b + pk0.x, prow2b + pk0.y };
            float accP1[4] = { prow2a + pk1.x, prow2a + pk1.y,
                               prow2b + pk1.x, prow2b + pk1.y };
            MMA1688(accP0, apd0, apd1, bpd0);
            MMA1688(accP1, apd0, apd1, bpd1);

            /* ---- feature side ---- */
            const float2 k0 = *(const float2*)(colcp + lc0);
            const float2 k1 = *(const float2*)(colcp + lc1);
            const float za0 = fmaf(accA[0], TWO_L2E, rowka + k0.x);
            const float za1 = fmaf(accA[1], TWO_L2E, rowka + k0.y);
            const float za2 = fmaf(accB[0], TWO_L2E, rowka + k1.x);
            const float za3 = fmaf(accB[1], TWO_L2E, rowka + k1.y);
            const float zb0 = fmaf(accA[2], TWO_L2E, rowkb + k0.x);
            const float zb1 = fmaf(accA[3], TWO_L2E, rowkb + k0.y);
            const float zb2 = fmaf(accB[2], TWO_L2E, rowkb + k1.x);
            const float zb3 = fmaf(accB[3], TWO_L2E, rowkb + k1.y);
            zfd0 += ex2_(za0) + ex2_(za1) + ex2_(za2) + ex2_(za3);
            zfd1 += ex2_(zb0) + ex2_(zb1) + ex2_(zb2) + ex2_(zb3);

            /* ---- pd near-pair path (acc = -d^2/2) ---- */
            {
                const float ma = fmaxf(fmaxf(accP0[0], accP0[1]),
                                       fmaxf(accP1[0], accP1[1]));
                if (ma > PDTH) {
                    float e;
                    e = ex2_(accP0[0] * TWOGL2E); zpd0 += e; tz0 = fmaf(e, za0, tz0);
                    e = ex2_(accP0[1] * TWOGL2E); zpd0 += e; tz0 = fmaf(e, za1, tz0);
                    e = ex2_(accP1[0] * TWOGL2E); zpd0 += e; tz0 = fmaf(e, za2, tz0);
                    e = ex2_(accP1[1] * TWOGL2E); zpd0 += e; tz0 = fmaf(e, za3, tz0);
                }
            }
            {
                const float mb = fmaxf(fmaxf(accP0[2], accP0[3]),
                                       fmaxf(accP1[2], accP1[3]));
                if (mb > PDTH) {
                    float e;
                    e = ex2_(accP0[2] * TWOGL2E); zpd1 += e; tz1 = fmaf(e, zb0, tz1);
                    e = ex2_(accP0[3] * TWOGL2E); zpd1 += e; tz1 = fmaf(e, zb1, tz1);
                    e = ex2_(accP1[2] * TWOGL2E); zpd1 += e; tz1 = fmaf(e, zb2, tz1);
                    e = ex2_(accP1[3] * TWOGL2E); zpd1 += e; tz1 = fmaf(e, zb3, tz1);
                }
            }
        }

        if (t + 1 < T_TILES) CPA_WAIT0();
        __syncthreads();
    }

    /* reduce quad lanes */
#pragma unroll
    for (int o = 1; o <= 2; o <<= 1) {
        zfd0 += __shfl_xor_sync(0xffffffffu, zfd0, o);
        zpd0 += __shfl_xor_sync(0xffffffffu, zpd0, o);
        tz0  += __shfl_xor_sync(0xffffffffu, tz0, o);
        zfd1 += __shfl_xor_sync(0xffffffffu, zfd1, o);
        zpd1 += __shfl_xor_sync(0xffffffffu, zpd1, o);
        tz1  += __shfl_xor_sync(0xffffffffu, tz1, o);
    }
    /* combine the two column halves via smem */
    float* red = (float*)(sm + OFF_RED);
    if (ch == 1 && q == 0) {
        red[r0] = zfd0;          red[r0 + 8] = zfd1;
        red[64 + r0] = zpd0;     red[64 + r0 + 8] = zpd1;
        red[128 + r0] = tz0;     red[128 + r0 + 8] = tz1;
    }
    __syncthreads();
    float val = 0.f;
    if (ch == 0 && q == 0) {
        const float ZF0 = zfd0 + red[r0];
        const float ZF1 = zfd1 + red[r0 + 8];
        const float ZP0 = zpd0 + red[64 + r0];
        const float ZP1 = zpd1 + red[64 + r0 + 8];
        const float TZ0 = tz0 + red[128 + r0];
        const float TZ1 = tz1 + red[128 + r0 + 8];
        const float TP0 = fmaf(TZ0, LN2, -SHIFT * ZP0);
        const float TP1 = fmaf(TZ1, LN2, -SHIFT * ZP1);
        const int na = b * NN + n0, nb_ = na + 8;
        const float ce0 = (logf(ZF0) - SHIFT) - TP0 / ZP0;
        const float ce1 = (logf(ZF1) - SHIFT) - TP1 / ZP1;
        val = w[na] * ce0 + w[nb_] * ce1;
    }
#pragma unroll
    for (int o = 16; o >= 4; o >>= 1) val += __shfl_down_sync(0xffffffffu, val, o);
    float* wsum = (float*)(sm + OFF_WSUM);
    if (lane == 0) wsum[wid] = val;
    __syncthreads();
    if (tid < 4) {
        float v = wsum[tid];
        v += __shfl_down_sync(0xfu, v, 2);
        v += __shfl_down_sync(0xfu, v, 1);
        if (tid == 0) g_cep[b * 64 + bx] = v;
    }

    /* ---- ticket: last CTA writes all 8 outputs ---- */
    __shared__ unsigned int lastTicket;
    __threadfence();
    if (tid == 0) lastTicket = atomicAdd(&g_ctr, 1u);
    __syncthreads();
    if (lastTicket == NCTA - 1) {
        __threadfence();
        float v = g_cep[tid];
#pragma unroll
        for (int o = 16; o > 0; o >>= 1) v += __shfl_down_sync(0xffffffffu, v, o);
        if (lane == 0) wsum[wid] = v;
        __syncthreads();
        if (tid < 4) out[tid] = wsum[2 * tid] + wsum[2 * tid + 1];
        if (tid >= 32 && tid < 96) {
            const int i = tid - 32;
            float r = g_regp[i];
#pragma unroll
            for (int o = 8; o > 0; o >>= 1) r += __shfl_down_sync(0xffffffffu, r, o, 16);
            if ((i & 15) == 0) out[4 + (i >> 4)] = r * (1.0f / (float)(NN * DD));
        }
        if (tid == 0) g_ctr = 0;
    }
}

/* -------------------------------- launcher ------------------------------- */
extern "C" void kernel_launch(void* const* d_in, const int* in_sizes, int n_in,
                              void* d_out, int out_size)
{
    const float* points = (const float*)d_in[0];
    const float* f1     = (const float*)d_in[1];
    const float* f2     = (const float*)d_in[2];
    const float* w      = (const float*)d_in[3];
    float* out          = (float*)d_out;

    static bool attr_set = false;
    if (!attr_set) {
        cudaFuncSetAttribute(ce_kernel, cudaFuncAttributeMaxDynamicSharedMemorySize, SMEM_CE);
        attr_set = true;
    }

    prep_kernel<<<BB * NN / 256, 256>>>(points, f1, f2);
    ce_kernel<<<dim3(NN / ROWS, BB), THREADS, SMEM_CE>>>(w, out);
}